// round 16
// baseline (speedup 1.0000x reference)
#include <cuda_runtime.h>
#include <cuda_bf16.h>
#include <cstdint>

// Problem constants
#define Bb   8
#define Cc   768
#define Nn   256
#define Hh   12
#define Dd   64
#define HN   3072          // Hh*Nn
#define CNsz 196608        // Cc*Nn
#define SCALE 0.125f       // D^-0.5
#define GNTS 12            // K tiles of 32 per split (K = 768, split 2-way)

// Scratch (allocation-free: __device__ globals)
__device__ __align__(16) float g_cp[Bb * CNsz];                // proj out [B,C,N]
__device__ __align__(16) float g_pp[2 * Bb * CNsz];            // split-K partials
__device__ __align__(16) float g_Mpart[Bb * Hh * Dd * Dd];     // per-(b,h) 64x64
__device__ __align__(16) __nv_bfloat16 g_Mth[Bb * Dd * Dd];    // M^T hi [b][d'][d], pre-scaled
__device__ __align__(16) __nv_bfloat16 g_Mtl[Bb * Dd * Dd];    // M^T lo
__device__ __align__(16) __nv_bfloat16 g_Uhi[Bb * Nn * Cc];    // U hi [B,N,C]
__device__ __align__(16) __nv_bfloat16 g_Ulo[Bb * Nn * Cc];    // U lo [B,N,C]

// ---- packed f32x2 helpers (for k_mpart) ----
#define FMA_F32X2(d, a, b, c) \
    asm("fma.rn.f32x2 %0, %1, %2, %3;" : "=l"(d) : "l"(a), "l"(b), "l"(c))

static __device__ __forceinline__ unsigned long long splat2(float x) {
    unsigned long long r;
    unsigned u = __float_as_uint(x);
    asm("mov.b64 %0, {%1, %1};" : "=l"(r) : "r"(u));
    return r;
}
static __device__ __forceinline__ float2 unpack2(unsigned long long v) {
    unsigned lo, hi;
    asm("mov.b64 {%0, %1}, %2;" : "=r"(lo), "=r"(hi) : "l"(v));
    return make_float2(__uint_as_float(lo), __uint_as_float(hi));
}

// ---- tensor-core primitives ----
static __device__ __forceinline__ uint32_t smem_u32(const void* p) {
    return (uint32_t)__cvta_generic_to_shared(p);
}

#define LDSM_X4(r0, r1, r2, r3, addr) \
    asm volatile("ldmatrix.sync.aligned.m8n8.x4.shared.b16 {%0,%1,%2,%3}, [%4];" \
        : "=r"(r0), "=r"(r1), "=r"(r2), "=r"(r3) : "r"(addr))

#define LDSM_X4_T(r0, r1, r2, r3, addr) \
    asm volatile("ldmatrix.sync.aligned.m8n8.x4.trans.shared.b16 {%0,%1,%2,%3}, [%4];" \
        : "=r"(r0), "=r"(r1), "=r"(r2), "=r"(r3) : "r"(addr))

#define MMA_BF16(D, a0, a1, a2, a3, b0, b1) \
    asm volatile("mma.sync.aligned.m16n8k16.row.col.f32.bf16.bf16.f32 " \
        "{%0,%1,%2,%3}, {%4,%5,%6,%7}, {%8,%9}, {%0,%1,%2,%3};" \
        : "+f"((D)[0]), "+f"((D)[1]), "+f"((D)[2]), "+f"((D)[3]) \
        : "r"(a0), "r"(a1), "r"(a2), "r"(a3), "r"(b0), "r"(b1))

// Split 8 fp32 -> bf16 hi chunk (16B) + bf16 lo chunk (16B)
static __device__ __forceinline__ void split8(float4 u, float4 v, uint4& hi, uint4& lo) {
    float f[8] = {u.x, u.y, u.z, u.w, v.x, v.y, v.z, v.w};
    uint32_t hw[4], lw[4];
#pragma unroll
    for (int i = 0; i < 4; i++) {
        __nv_bfloat16 h0 = __float2bfloat16(f[2 * i]);
        __nv_bfloat16 h1 = __float2bfloat16(f[2 * i + 1]);
        __nv_bfloat16 l0 = __float2bfloat16(f[2 * i] - __bfloat162float(h0));
        __nv_bfloat16 l1 = __float2bfloat16(f[2 * i + 1] - __bfloat162float(h1));
        __nv_bfloat162 hh(h0, h1), ll(l0, l1);
        hw[i] = *reinterpret_cast<uint32_t*>(&hh);
        lw[i] = *reinterpret_cast<uint32_t*>(&ll);
    }
    hi = make_uint4(hw[0], hw[1], hw[2], hw[3]);
    lo = make_uint4(lw[0], lw[1], lw[2], lw[3]);
}

// Three-pass MMA emission
#define EMIT_MMAS_3PASS(acc_, ah_, al_, bh_, bl_)                             \
    _Pragma("unroll")                                                         \
    for (int np = 0; np < 2; np++)                                            \
        _Pragma("unroll")                                                     \
        for (int mf = 0; mf < 2; mf++) {                                      \
            MMA_BF16(acc_[mf][2 * np], ah_[mf][0], ah_[mf][1], ah_[mf][2], ah_[mf][3], bh_[np][0], bh_[np][1]); \
            MMA_BF16(acc_[mf][2 * np + 1], ah_[mf][0], ah_[mf][1], ah_[mf][2], ah_[mf][3], bh_[np][2], bh_[np][3]); \
        }                                                                     \
    _Pragma("unroll")                                                         \
    for (int np = 0; np < 2; np++)                                            \
        _Pragma("unroll")                                                     \
        for (int mf = 0; mf < 2; mf++) {                                      \
            MMA_BF16(acc_[mf][2 * np], al_[mf][0], al_[mf][1], al_[mf][2], al_[mf][3], bh_[np][0], bh_[np][1]); \
            MMA_BF16(acc_[mf][2 * np + 1], al_[mf][0], al_[mf][1], al_[mf][2], al_[mf][3], bh_[np][2], bh_[np][3]); \
        }                                                                     \
    _Pragma("unroll")                                                         \
    for (int np = 0; np < 2; np++)                                            \
        _Pragma("unroll")                                                     \
        for (int mf = 0; mf < 2; mf++) {                                      \
            MMA_BF16(acc_[mf][2 * np], ah_[mf][0], ah_[mf][1], ah_[mf][2], ah_[mf][3], bl_[np][0], bl_[np][1]); \
            MMA_BF16(acc_[mf][2 * np + 1], ah_[mf][0], ah_[mf][1], ah_[mf][2], ah_[mf][3], bl_[np][2], bl_[np][3]); \
        }

// ============================================================================
// Kernel 1: split-K proj partials: pp[z] = W_proj[:, zK:] @ cross[zK:, :].
// 128x64 double-buffered winner skeleton; 12 k-tiles; grid (32, 6, 2).
// ============================================================================
__global__ __launch_bounds__(256, 2) void k_proj_mma(
    const float* __restrict__ W, const float* __restrict__ cross)
{
    __shared__ uint4 As4[2][128][8];
    __shared__ uint4 Bs4[2][64][8];
    const int tid = threadIdx.x;
    const int wid = tid >> 5, lane = tid & 31;
    const int b = blockIdx.x >> 2;
    const int noff = (blockIdx.x & 3) * 64;
    const int otile = blockIdx.y * 128;
    const int kbase = blockIdx.z * 384;
    float* dst = g_pp + (size_t)blockIdx.z * (Bb * CNsz);

    const int wm = (wid >> 1) * 32;
    const int wn = (wid & 1) * 32;
    const int l7 = lane & 7, l15 = lane & 15, lsel = lane >> 4;
    const int g = lane >> 2, tc = lane & 3;

    const int arow = tid >> 2, akseg = tid & 3;
    const int am7 = arow & 7;
    const int bkrow = tid >> 3, bnseg = tid & 7;
    const int bk7 = bkrow & 7;

    const float* Agp = W + (size_t)(otile + arow) * Cc + kbase + akseg * 8;
    const float* Bgp = cross + (size_t)b * CNsz + (size_t)(kbase + bkrow) * Nn + noff + bnseg * 8;

    const uint32_t as_base = smem_u32(&As4[0][0][0]);
    const uint32_t bs_base = smem_u32(&Bs4[0][0][0]);

    float acc[2][4][4];
#pragma unroll
    for (int i = 0; i < 2; i++)
#pragma unroll
        for (int j = 0; j < 4; j++)
#pragma unroll
            for (int e = 0; e < 4; e++) acc[i][j][e] = 0.f;

    float4 a0[2], a1[2], bv[2];
    a0[0] = *(const float4*)(Agp);
    a0[1] = *(const float4*)(Agp + 4);
    a1[0] = *(const float4*)(Agp + (size_t)64 * Cc);
    a1[1] = *(const float4*)(Agp + (size_t)64 * Cc + 4);
    bv[0] = *(const float4*)(Bgp);
    bv[1] = *(const float4*)(Bgp + 4);

    {
        uint4 h, l;
        split8(a0[0], a0[1], h, l);
        As4[0][arow][akseg ^ am7] = h;
        As4[0][arow][(akseg + 4) ^ am7] = l;
        split8(a1[0], a1[1], h, l);
        As4[0][arow + 64][akseg ^ am7] = h;
        As4[0][arow + 64][(akseg + 4) ^ am7] = l;
        split8(bv[0], bv[1], h, l);
        Bs4[0][bkrow][bnseg ^ bk7] = h;
        Bs4[0][bkrow + 32][bnseg ^ bk7] = l;
    }
    __syncthreads();

    for (int kt = 0; kt < GNTS; kt++) {
        const int cur = kt & 1;
        if (kt + 1 < GNTS) {
            Agp += 32;
            Bgp += (size_t)32 * Nn;
            a0[0] = *(const float4*)(Agp);
            a0[1] = *(const float4*)(Agp + 4);
            a1[0] = *(const float4*)(Agp + (size_t)64 * Cc);
            a1[1] = *(const float4*)(Agp + (size_t)64 * Cc + 4);
            bv[0] = *(const float4*)(Bgp);
            bv[1] = *(const float4*)(Bgp + 4);
        }

        const uint32_t asb = as_base + (uint32_t)cur * 16384;
        const uint32_t bsb = bs_base + (uint32_t)cur * 8192;
#pragma unroll
        for (int ks = 0; ks < 2; ks++) {
            const int k0 = ks * 16;
            uint32_t ah[2][4], al[2][4], bhv[2][4], blv[2][4];
#pragma unroll
            for (int mf = 0; mf < 2; mf++) {
                const uint32_t rbase = asb + (uint32_t)(wm + mf * 16 + l15) * 128;
                const int ch = ((k0 >> 3) + lsel) ^ l7;
                const int cl = ((k0 >> 3) + lsel + 4) ^ l7;
                LDSM_X4(ah[mf][0], ah[mf][1], ah[mf][2], ah[mf][3], rbase + ch * 16);
                LDSM_X4(al[mf][0], al[mf][1], al[mf][2], al[mf][3], rbase + cl * 16);
            }
#pragma unroll
            for (int np = 0; np < 2; np++) {
                const int c = (wn >> 3) + np * 2 + lsel;
                const int p = c ^ l7;
                const uint32_t rb = bsb + (uint32_t)(k0 + l15) * 128 + p * 16;
                LDSM_X4_T(bhv[np][0], bhv[np][1], bhv[np][2], bhv[np][3], rb);
                LDSM_X4_T(blv[np][0], blv[np][1], blv[np][2], blv[np][3], rb + 32 * 128);
            }
            EMIT_MMAS_3PASS(acc, ah, al, bhv, blv)
        }

        if (kt + 1 < GNTS) {
            const int nxt = cur ^ 1;
            uint4 h, l;
            split8(a0[0], a0[1], h, l);
            As4[nxt][arow][akseg ^ am7] = h;
            As4[nxt][arow][(akseg + 4) ^ am7] = l;
            split8(a1[0], a1[1], h, l);
            As4[nxt][arow + 64][akseg ^ am7] = h;
            As4[nxt][arow + 64][(akseg + 4) ^ am7] = l;
            split8(bv[0], bv[1], h, l);
            Bs4[nxt][bkrow][bnseg ^ bk7] = h;
            Bs4[nxt][bkrow + 32][bnseg ^ bk7] = l;
            __syncthreads();
        }
    }

    // Epilogue: raw partial write
#pragma unroll
    for (int mf = 0; mf < 2; mf++) {
        const int o = otile + wm + mf * 16 + g;
        float* base = dst + (size_t)b * CNsz + (size_t)o * Nn + noff + wn + tc * 2;
#pragma unroll
        for (int nf = 0; nf < 4; nf++) {
            *(float2*)(base + nf * 8) = make_float2(acc[mf][nf][0], acc[mf][nf][1]);
            *(float2*)(base + nf * 8 + 8 * Nn) = make_float2(acc[mf][nf][2], acc[mf][nf][3]);
        }
    }
}

// ============================================================================
// Kernel 1b: g_cp = pp0 + pp1 + bias
// ============================================================================
__global__ __launch_bounds__(256) void k_red_proj(const float* __restrict__ bias)
{
    const int i4 = blockIdx.x * 256 + threadIdx.x;   // 393216 float4s
    const int o = (i4 >> 6) % Cc;
    const float bo = bias[o];
    float4 p0 = ((const float4*)g_pp)[i4];
    float4 p1 = ((const float4*)(g_pp + (size_t)Bb * CNsz))[i4];
    ((float4*)g_cp)[i4] = make_float4(p0.x + p1.x + bo, p0.y + p1.y + bo,
                                      p0.z + p1.z + bo, p0.w + p1.w + bo);
}

// ============================================================================
// Kernel 2: Mpart[b,h][d,d'] = sum_n cp[b,d*H+h,n] * cross[b,d'*H+h,n]
// ============================================================================
__global__ __launch_bounds__(256) void k_mpart(const float* __restrict__ cross)
{
    __shared__ float As[16][64];
    __shared__ float Bs[16][64];
    const int h = blockIdx.x;
    const int b = blockIdx.y;
    const int tid = threadIdx.x;
    const int r = tid >> 4, c = tid & 15;
    const int lr = tid >> 2, lk = (tid & 3) * 4;

    const float* Ab = g_cp + (size_t)b * CNsz + h * Nn;
    const float* Bp = cross + (size_t)b * CNsz + h * Nn;

    unsigned long long acc[4][2];
#pragma unroll
    for (int i = 0; i < 4; i++) { acc[i][0] = 0ull; acc[i][1] = 0ull; }

    for (int k0 = 0; k0 < Nn; k0 += 16) {
        float4 av = *(const float4*)(Ab + (size_t)lr * HN + k0 + lk);
        float4 bv = *(const float4*)(Bp + (size_t)lr * HN + k0 + lk);
        __syncthreads();
        As[lk + 0][lr] = av.x; As[lk + 1][lr] = av.y;
        As[lk + 2][lr] = av.z; As[lk + 3][lr] = av.w;
        Bs[lk + 0][lr] = bv.x; Bs[lk + 1][lr] = bv.y;
        Bs[lk + 2][lr] = bv.z; Bs[lk + 3][lr] = bv.w;
        __syncthreads();
#pragma unroll
        for (int k = 0; k < 16; k++) {
            float4 ar = *(const float4*)&As[k][r * 4];
            ulonglong2 bp = *(const ulonglong2*)&Bs[k][c * 4];
            unsigned long long sv;
            sv = splat2(ar.x);
            FMA_F32X2(acc[0][0], sv, bp.x, acc[0][0]);
            FMA_F32X2(acc[0][1], sv, bp.y, acc[0][1]);
            sv = splat2(ar.y);
            FMA_F32X2(acc[1][0], sv, bp.x, acc[1][0]);
            FMA_F32X2(acc[1][1], sv, bp.y, acc[1][1]);
            sv = splat2(ar.z);
            FMA_F32X2(acc[2][0], sv, bp.x, acc[2][0]);
            FMA_F32X2(acc[2][1], sv, bp.y, acc[2][1]);
            sv = splat2(ar.w);
            FMA_F32X2(acc[3][0], sv, bp.x, acc[3][0]);
            FMA_F32X2(acc[3][1], sv, bp.y, acc[3][1]);
        }
    }

    float* mp = g_Mpart + ((size_t)b * Hh + h) * 4096;
#pragma unroll
    for (int i = 0; i < 4; i++) {
        float2 lo = unpack2(acc[i][0]);
        float2 hi = unpack2(acc[i][1]);
        *(float4*)(mp + (size_t)(r * 4 + i) * 64 + c * 4) =
            make_float4(lo.x, lo.y, hi.x, hi.y);
    }
}

// ============================================================================
// Kernel 2b: Mt planes = split(SCALE * sum_h Mpart[b,h])^T, [b][d'][d] bf16.
// ============================================================================
__global__ __launch_bounds__(256) void k_mred_t()
{
    const int idx = blockIdx.x * 256 + threadIdx.x;
    const int b = idx >> 12;
    const int e = idx & 4095;
    const int d = e >> 6, dp = e & 63;
    float s = 0.f;
#pragma unroll
    for (int h = 0; h < Hh; h++)
        s += g_Mpart[((size_t)b * Hh + h) * 4096 + e];
    s *= SCALE;
    __nv_bfloat16 hv = __float2bfloat16(s);
    __nv_bfloat16 lv = __float2bfloat16(s - __bfloat162float(hv));
    g_Mth[(size_t)b * 4096 + dp * 64 + d] = hv;
    g_Mtl[(size_t)b * 4096 + dp * 64 + d] = lv;
}

// ============================================================================
// Kernel 3: k_out_mma — U[m, d'] = sum_d X[d,m] * M[d,d'] on tensor cores.
// ============================================================================
__global__ __launch_bounds__(256) void k_out_mma(const float* __restrict__ x_ori)
{
    __shared__ uint4 As4[128][16];
    __shared__ uint4 BsH[64][8];
    __shared__ uint4 BsL[64][8];
    const int tid = threadIdx.x;
    const int wid = tid >> 5, lane = tid & 31;
    const int b = blockIdx.x / Hh;
    const int h = blockIdx.x % Hh;
    const int mhalf = blockIdx.y;

    const int wm = (wid >> 1) * 32;
    const int wn = (wid & 1) * 32;
    const int l7 = lane & 7, l15 = lane & 15, lsel = lane >> 4;
    const int ksel = (lane >> 3) & 1;
    const int rowNl = (lane & 7) + (lsel << 3);
    const int g = lane >> 2, tc = lane & 3;

    {
        const int d = tid >> 2;
        const int mseg = (tid & 3) * 32;
        const int d7 = d & 7;
        const float* xr = x_ori + (size_t)b * CNsz + (size_t)(d * Hh + h) * Nn
                          + mhalf * 128 + mseg;
        float4 v[8];
#pragma unroll
        for (int j = 0; j < 8; j++) v[j] = ((const float4*)xr)[j];
#pragma unroll
        for (int j = 0; j < 4; j++) {
            uint4 hi, lo;
            split8(v[2 * j], v[2 * j + 1], hi, lo);
            const int c = (mseg >> 3) + j;
            const int p = (c & 8) | ((c ^ d7) & 7);
            As4[d][p] = hi;
            As4[d + 64][p] = lo;
        }
    }
    {
#pragma unroll
        for (int r = 0; r < 2; r++) {
            const int i = tid + r * 256;
            const int dp = i >> 3, c = i & 7;
            const int p = c ^ (dp & 7);
            BsH[dp][p] = ((const uint4*)(g_Mth + (size_t)b * 4096))[i];
            BsL[dp][p] = ((const uint4*)(g_Mtl + (size_t)b * 4096))[i];
        }
    }
    __syncthreads();

    const uint32_t asb = smem_u32(&As4[0][0]);
    const uint32_t bhb = smem_u32(&BsH[0][0]);
    const uint32_t blb = smem_u32(&BsL[0][0]);

    float acc[2][4][4];
#pragma unroll
    for (int i = 0; i < 2; i++)
#pragma unroll
        for (int j = 0; j < 4; j++)
#pragma unroll
            for (int e = 0; e < 4; e++) acc[i][j][e] = 0.f;

#pragma unroll
    for (int ks = 0; ks < 4; ks++) {
        uint32_t ah[2][4], al[2][4], bhv[2][4], blv[2][4];
#pragma unroll
        for (int mf = 0; mf < 2; mf++) {
            const int c = ((wm + mf * 16) >> 3) + lsel;
            const int p = (c & 8) | ((c ^ l7) & 7);
            const uint32_t rowk = (uint32_t)(ks * 16 + l15);
            uint32_t t0, t1, t2, t3;
            LDSM_X4_T(t0, t1, t2, t3, asb + rowk * 256 + p * 16);
            ah[mf][0] = t0; ah[mf][1] = t2; ah[mf][2] = t1; ah[mf][3] = t3;
            LDSM_X4_T(t0, t1, t2, t3, asb + (rowk + 64) * 256 + p * 16);
            al[mf][0] = t0; al[mf][1] = t2; al[mf][2] = t1; al[mf][3] = t3;
        }
#pragma unroll
        for (int np = 0; np < 2; np++) {
            const int rowN = wn + np * 16 + rowNl;
            const int ch = (ks * 2 + ksel) ^ l7;
            LDSM_X4(bhv[np][0], bhv[np][1], bhv[np][2], bhv[np][3],
                    bhb + (uint32_t)rowN * 128 + ch * 16);
            LDSM_X4(blv[np][0], blv[np][1], blv[np][2], blv[np][3],
                    blb + (uint32_t)rowN * 128 + ch * 16);
        }
        EMIT_MMAS_3PASS(acc, ah, al, bhv, blv)
    }

    const int mbase = h * 256 + mhalf * 128;
#pragma unroll
    for (int mf = 0; mf < 2; mf++) {
#pragma unroll
        for (int rh = 0; rh < 2; rh++) {
            const int m = mbase + wm + mf * 16 + g + rh * 8;
            const int nf = m / Hh;
            const int hf = m - nf * Hh;
            const size_t rowoff = ((size_t)b * Nn + nf) * Cc + hf * Dd + wn + tc * 2;
#pragma unroll
            for (int j = 0; j < 4; j++) {
                const float e0 = acc[mf][j][2 * rh];
                const float e1 = acc[mf][j][2 * rh + 1];
                __nv_bfloat16 h0 = __float2bfloat16(e0);
                __nv_bfloat16 h1 = __float2bfloat16(e1);
                __nv_bfloat16 l0 = __float2bfloat16(e0 - __bfloat162float(h0));
                __nv_bfloat16 l1 = __float2bfloat16(e1 - __bfloat162float(h1));
                __nv_bfloat162 hh(h0, h1), ll(l0, l1);
                *(uint32_t*)(g_Uhi + rowoff + j * 8) = *reinterpret_cast<uint32_t*>(&hh);
                *(uint32_t*)(g_Ulo + rowoff + j * 8) = *reinterpret_cast<uint32_t*>(&ll);
            }
        }
    }
}

// ============================================================================
// Kernel 4: split-K deproj partials: pp[z] = U[:, zK:] @ W_dep[:, zK:]^T.
// Grid (32, 6, 2).
// ============================================================================
__global__ __launch_bounds__(256, 2) void k_deproj_mma(const float* __restrict__ Wdep)
{
    __shared__ uint4 As4[2][128][8];
    __shared__ uint4 Bs4[2][64][8];
    const int tid = threadIdx.x;
    const int wid = tid >> 5, lane = tid & 31;
    const int b = blockIdx.x >> 2;
    const int noff = (blockIdx.x & 3) * 64;
    const int otile = blockIdx.y * 128;
    const int kbase = blockIdx.z * 384;
    float* dst = g_pp + (size_t)blockIdx.z * (Bb * CNsz);

    const int wm = (wid >> 1) * 32;
    const int wn = (wid & 1) * 32;
    const int l7 = lane & 7, l15 = lane & 15, lsel = lane >> 4;
    const int ksel = (lane >> 3) & 1;
    const int rowNl = (lane & 7) + (lsel << 3);
    const int g = lane >> 2, tc = lane & 3;

    const int arow = tid >> 2, akseg = tid & 3;
    const int am7 = arow & 7;
    const int bnrow = tid >> 3, bc = tid & 7;
    const int bn7 = bnrow & 7;

    const float* Agp = Wdep + (size_t)(otile + arow) * Cc + kbase + akseg * 8;
    const __nv_bfloat16* Usrc = (bc < 4) ? g_Uhi : g_Ulo;
    const __nv_bfloat16* Ugp =
        Usrc + ((size_t)b * Nn + noff + bnrow) * Cc + kbase + (bc & 3) * 8;

    const uint32_t as_base = smem_u32(&As4[0][0][0]);
    const uint32_t bs_base = smem_u32(&Bs4[0][0][0]);

    float acc[2][4][4];
#pragma unroll
    for (int i = 0; i < 2; i++)
#pragma unroll
        for (int j = 0; j < 4; j++)
#pragma unroll
            for (int e = 0; e < 4; e++) acc[i][j][e] = 0.f;

    float4 a0[2], a1[2];
    uint4 u0, u1;
    a0[0] = *(const float4*)(Agp);
    a0[1] = *(const float4*)(Agp + 4);
    a1[0] = *(const float4*)(Agp + (size_t)64 * Cc);
    a1[1] = *(const float4*)(Agp + (size_t)64 * Cc + 4);
    u0 = *(const uint4*)(Ugp);
    u1 = *(const uint4*)(Ugp + (size_t)32 * Cc);

    {
        uint4 h, l;
        split8(a0[0], a0[1], h, l);
        As4[0][arow][akseg ^ am7] = h;
        As4[0][arow][(akseg + 4) ^ am7] = l;
        split8(a1[0], a1[1], h, l);
        As4[0][arow + 64][akseg ^ am7] = h;
        As4[0][arow + 64][(akseg + 4) ^ am7] = l;
        Bs4[0][bnrow][bc ^ bn7] = u0;
        Bs4[0][bnrow + 32][bc ^ bn7] = u1;
    }
    __syncthreads();

    for (int kt = 0; kt < GNTS; kt++) {
        const int cur = kt & 1;
        if (kt + 1 < GNTS) {
            Agp += 32;
            Ugp += 32;
            a0[0] = *(const float4*)(Agp);
            a0[1] = *(const float4*)(Agp + 4);
            a1[0] = *(const float4*)(Agp + (size_t)64 * Cc);
            a1[1] = *(const float4*)(Agp + (size_t)64 * Cc + 4);
            u0 = *(const uint4*)(Ugp);
            u1 = *(const uint4*)(Ugp + (size_t)32 * Cc);
        }

        const uint32_t asb = as_base + (uint32_t)cur * 16384;
        const uint32_t bsb = bs_base + (uint32_t)cur * 8192;
#pragma unroll
        for (int ks = 0; ks < 2; ks++) {
            const int k0 = ks * 16;
            uint32_t ah[2][4], al[2][4], bhv[2][4], blv[2][4];
#pragma unroll
            for (int mf = 0; mf < 2; mf++) {
                const uint32_t rbase = asb + (uint32_t)(wm + mf * 16 + l15) * 128;
                const int ch = ((k0 >> 3) + lsel) ^ l7;
                const int cl = ((k0 >> 3) + lsel + 4) ^ l7;
                LDSM_X4(ah[mf][0], ah[mf][1], ah[mf][2], ah[mf][3], rbase + ch * 16);
                LDSM_X4(al[mf][0], al[mf][1], al[mf][2], al[mf][3], rbase + cl * 16);
            }
#pragma unroll
            for (int np = 0; np < 2; np++) {
                const int rowN = wn + np * 16 + rowNl;
                const int ch = ((k0 >> 3) + ksel) ^ l7;
                const int cl = ((k0 >> 3) + ksel + 4) ^ l7;
                const uint32_t rb = bsb + (uint32_t)rowN * 128;
                LDSM_X4(bhv[np][0], bhv[np][1], bhv[np][2], bhv[np][3], rb + ch * 16);
                LDSM_X4(blv[np][0], blv[np][1], blv[np][2], blv[np][3], rb + cl * 16);
            }
            EMIT_MMAS_3PASS(acc, ah, al, bhv, blv)
        }

        if (kt + 1 < GNTS) {
            const int nxt = cur ^ 1;
            uint4 h, l;
            split8(a0[0], a0[1], h, l);
            As4[nxt][arow][akseg ^ am7] = h;
            As4[nxt][arow][(akseg + 4) ^ am7] = l;
            split8(a1[0], a1[1], h, l);
            As4[nxt][arow + 64][akseg ^ am7] = h;
            As4[nxt][arow + 64][(akseg + 4) ^ am7] = l;
            Bs4[nxt][bnrow][bc ^ bn7] = u0;
            Bs4[nxt][bnrow + 32][bc ^ bn7] = u1;
            __syncthreads();
        }
    }

    // Epilogue: raw partial write
#pragma unroll
    for (int mf = 0; mf < 2; mf++) {
        const int o = otile + wm + mf * 16 + g;
        float* base = dst + (size_t)b * CNsz + (size_t)o * Nn + noff + wn + tc * 2;
#pragma unroll
        for (int nf = 0; nf < 4; nf++) {
            *(float2*)(base + nf * 8) = make_float2(acc[mf][nf][0], acc[mf][nf][1]);
            *(float2*)(base + nf * 8 + 8 * Nn) = make_float2(acc[mf][nf][2], acc[mf][nf][3]);
        }
    }
}

// ============================================================================
// Kernel 4b: out = pp0 + pp1 + bias + x_ori
// ============================================================================
__global__ __launch_bounds__(256) void k_red_dep(
    const float* __restrict__ bias, const float* __restrict__ x_ori,
    float* __restrict__ out)
{
    const int i4 = blockIdx.x * 256 + threadIdx.x;   // 393216 float4s
    const int o = (i4 >> 6) % Cc;
    const float bo = bias[o];
    float4 p0 = ((const float4*)g_pp)[i4];
    float4 p1 = ((const float4*)(g_pp + (size_t)Bb * CNsz))[i4];
    float4 xv = ((const float4*)x_ori)[i4];
    ((float4*)out)[i4] = make_float4(p0.x + p1.x + bo + xv.x,
                                     p0.y + p1.y + bo + xv.y,
                                     p0.z + p1.z + bo + xv.z,
                                     p0.w + p1.w + bo + xv.w);
}

// ============================================================================
// Launch
// ============================================================================
extern "C" void kernel_launch(void* const* d_in, const int* in_sizes, int n_in,
                              void* d_out, int out_size)
{
    (void)in_sizes; (void)n_in; (void)out_size;
    const float* x_ori  = (const float*)d_in[0];
    const float* cross  = (const float*)d_in[1];
    const float* W_proj = (const float*)d_in[2];
    const float* b_proj = (const float*)d_in[3];
    const float* W_dep  = (const float*)d_in[4];
    const float* b_dep  = (const float*)d_in[5];
    float* out = (float*)d_out;

    k_proj_mma<<<dim3(32, 6, 2), 256>>>(W_proj, cross);
    k_red_proj<<<1536, 256>>>(b_proj);
    k_mpart<<<dim3(Hh, Bb), 256>>>(cross);
    k_mred_t<<<128, 256>>>();
    k_out_mma<<<dim3(Bb * Hh, 2), 256>>>(x_ori);
    k_deproj_mma<<<dim3(32, 6, 2), 256>>>(W_dep);
    k_red_dep<<<1536, 256>>>(b_dep, x_ori, out);
}

// round 17
// speedup vs baseline: 1.3818x; 1.3818x over previous
#include <cuda_runtime.h>
#include <cuda_bf16.h>
#include <cstdint>

// Problem constants
#define Bb   8
#define Cc   768
#define Nn   256
#define Hh   12
#define Dd   64
#define HN   3072          // Hh*Nn
#define CNsz 196608        // Cc*Nn
#define SCALE 0.125f       // D^-0.5
#define GNT  24            // K tiles of 32 (K = 768)

// Scratch (allocation-free: __device__ globals)
__device__ __align__(16) float g_cp[Bb * CNsz];                // proj out [B,C,N]
__device__ __align__(16) float g_Mpart[Bb * Hh * Dd * Dd];     // per-(b,h) 64x64
__device__ __align__(16) __nv_bfloat16 g_Mth[Bb * Dd * Dd];    // M^T hi [b][d'][d], pre-scaled
__device__ __align__(16) __nv_bfloat16 g_Mtl[Bb * Dd * Dd];    // M^T lo
__device__ __align__(16) __nv_bfloat16 g_Uhi[Bb * Nn * Cc];    // U hi [B,N,C]
__device__ __align__(16) __nv_bfloat16 g_Ulo[Bb * Nn * Cc];    // U lo [B,N,C]

// ---- packed f32x2 helpers (for k_mpart) ----
#define FMA_F32X2(d, a, b, c) \
    asm("fma.rn.f32x2 %0, %1, %2, %3;" : "=l"(d) : "l"(a), "l"(b), "l"(c))

static __device__ __forceinline__ unsigned long long splat2(float x) {
    unsigned long long r;
    unsigned u = __float_as_uint(x);
    asm("mov.b64 %0, {%1, %1};" : "=l"(r) : "r"(u));
    return r;
}
static __device__ __forceinline__ float2 unpack2(unsigned long long v) {
    unsigned lo, hi;
    asm("mov.b64 {%0, %1}, %2;" : "=r"(lo), "=r"(hi) : "l"(v));
    return make_float2(__uint_as_float(lo), __uint_as_float(hi));
}

// ---- tensor-core primitives ----
static __device__ __forceinline__ uint32_t smem_u32(const void* p) {
    return (uint32_t)__cvta_generic_to_shared(p);
}

#define LDSM_X4(r0, r1, r2, r3, addr) \
    asm volatile("ldmatrix.sync.aligned.m8n8.x4.shared.b16 {%0,%1,%2,%3}, [%4];" \
        : "=r"(r0), "=r"(r1), "=r"(r2), "=r"(r3) : "r"(addr))

#define LDSM_X4_T(r0, r1, r2, r3, addr) \
    asm volatile("ldmatrix.sync.aligned.m8n8.x4.trans.shared.b16 {%0,%1,%2,%3}, [%4];" \
        : "=r"(r0), "=r"(r1), "=r"(r2), "=r"(r3) : "r"(addr))

#define MMA_BF16(D, a0, a1, a2, a3, b0, b1) \
    asm volatile("mma.sync.aligned.m16n8k16.row.col.f32.bf16.bf16.f32 " \
        "{%0,%1,%2,%3}, {%4,%5,%6,%7}, {%8,%9}, {%0,%1,%2,%3};" \
        : "+f"((D)[0]), "+f"((D)[1]), "+f"((D)[2]), "+f"((D)[3]) \
        : "r"(a0), "r"(a1), "r"(a2), "r"(a3), "r"(b0), "r"(b1))

// Split 8 fp32 -> bf16 hi chunk (16B) + bf16 lo chunk (16B)
static __device__ __forceinline__ void split8(float4 u, float4 v, uint4& hi, uint4& lo) {
    float f[8] = {u.x, u.y, u.z, u.w, v.x, v.y, v.z, v.w};
    uint32_t hw[4], lw[4];
#pragma unroll
    for (int i = 0; i < 4; i++) {
        __nv_bfloat16 h0 = __float2bfloat16(f[2 * i]);
        __nv_bfloat16 h1 = __float2bfloat16(f[2 * i + 1]);
        __nv_bfloat16 l0 = __float2bfloat16(f[2 * i] - __bfloat162float(h0));
        __nv_bfloat16 l1 = __float2bfloat16(f[2 * i + 1] - __bfloat162float(h1));
        __nv_bfloat162 hh(h0, h1), ll(l0, l1);
        hw[i] = *reinterpret_cast<uint32_t*>(&hh);
        lw[i] = *reinterpret_cast<uint32_t*>(&ll);
    }
    hi = make_uint4(hw[0], hw[1], hw[2], hw[3]);
    lo = make_uint4(lw[0], lw[1], lw[2], lw[3]);
}

// Three-pass MMA emission
#define EMIT_MMAS_3PASS(acc_, ah_, al_, bh_, bl_)                             \
    _Pragma("unroll")                                                         \
    for (int np = 0; np < 2; np++)                                            \
        _Pragma("unroll")                                                     \
        for (int mf = 0; mf < 2; mf++) {                                      \
            MMA_BF16(acc_[mf][2 * np], ah_[mf][0], ah_[mf][1], ah_[mf][2], ah_[mf][3], bh_[np][0], bh_[np][1]); \
            MMA_BF16(acc_[mf][2 * np + 1], ah_[mf][0], ah_[mf][1], ah_[mf][2], ah_[mf][3], bh_[np][2], bh_[np][3]); \
        }                                                                     \
    _Pragma("unroll")                                                         \
    for (int np = 0; np < 2; np++)                                            \
        _Pragma("unroll")                                                     \
        for (int mf = 0; mf < 2; mf++) {                                      \
            MMA_BF16(acc_[mf][2 * np], al_[mf][0], al_[mf][1], al_[mf][2], al_[mf][3], bh_[np][0], bh_[np][1]); \
            MMA_BF16(acc_[mf][2 * np + 1], al_[mf][0], al_[mf][1], al_[mf][2], al_[mf][3], bh_[np][2], bh_[np][3]); \
        }                                                                     \
    _Pragma("unroll")                                                         \
    for (int np = 0; np < 2; np++)                                            \
        _Pragma("unroll")                                                     \
        for (int mf = 0; mf < 2; mf++) {                                      \
            MMA_BF16(acc_[mf][2 * np], ah_[mf][0], ah_[mf][1], ah_[mf][2], ah_[mf][3], bl_[np][0], bl_[np][1]); \
            MMA_BF16(acc_[mf][2 * np + 1], ah_[mf][0], ah_[mf][1], ah_[mf][2], ah_[mf][3], bl_[np][2], bl_[np][3]); \
        }

// ============================================================================
// Kernel 1: cp = W_proj @ cross + b_proj, bf16 3-split tensor core.
// 128x64 double-buffered winner skeleton. Grid (32, 6).
// ============================================================================
__global__ __launch_bounds__(256, 2) void k_proj_mma(
    const float* __restrict__ W, const float* __restrict__ cross,
    const float* __restrict__ bias)
{
    __shared__ uint4 As4[2][128][8];
    __shared__ uint4 Bs4[2][64][8];
    const int tid = threadIdx.x;
    const int wid = tid >> 5, lane = tid & 31;
    const int b = blockIdx.x >> 2;
    const int noff = (blockIdx.x & 3) * 64;
    const int otile = blockIdx.y * 128;

    const int wm = (wid >> 1) * 32;
    const int wn = (wid & 1) * 32;
    const int l7 = lane & 7, l15 = lane & 15, lsel = lane >> 4;
    const int g = lane >> 2, tc = lane & 3;

    const int arow = tid >> 2, akseg = tid & 3;
    const int am7 = arow & 7;
    const int bkrow = tid >> 3, bnseg = tid & 7;
    const int bk7 = bkrow & 7;

    const float* Agp = W + (size_t)(otile + arow) * Cc + akseg * 8;
    const float* Bgp = cross + (size_t)b * CNsz + (size_t)bkrow * Nn + noff + bnseg * 8;

    const uint32_t as_base = smem_u32(&As4[0][0][0]);
    const uint32_t bs_base = smem_u32(&Bs4[0][0][0]);

    float acc[2][4][4];
#pragma unroll
    for (int i = 0; i < 2; i++)
#pragma unroll
        for (int j = 0; j < 4; j++)
#pragma unroll
            for (int e = 0; e < 4; e++) acc[i][j][e] = 0.f;

    float4 a0[2], a1[2], bv[2];
    a0[0] = *(const float4*)(Agp);
    a0[1] = *(const float4*)(Agp + 4);
    a1[0] = *(const float4*)(Agp + (size_t)64 * Cc);
    a1[1] = *(const float4*)(Agp + (size_t)64 * Cc + 4);
    bv[0] = *(const float4*)(Bgp);
    bv[1] = *(const float4*)(Bgp + 4);

    {
        uint4 h, l;
        split8(a0[0], a0[1], h, l);
        As4[0][arow][akseg ^ am7] = h;
        As4[0][arow][(akseg + 4) ^ am7] = l;
        split8(a1[0], a1[1], h, l);
        As4[0][arow + 64][akseg ^ am7] = h;
        As4[0][arow + 64][(akseg + 4) ^ am7] = l;
        split8(bv[0], bv[1], h, l);
        Bs4[0][bkrow][bnseg ^ bk7] = h;
        Bs4[0][bkrow + 32][bnseg ^ bk7] = l;
    }
    __syncthreads();

    for (int kt = 0; kt < GNT; kt++) {
        const int cur = kt & 1;
        if (kt + 1 < GNT) {
            Agp += 32;
            Bgp += (size_t)32 * Nn;
            a0[0] = *(const float4*)(Agp);
            a0[1] = *(const float4*)(Agp + 4);
            a1[0] = *(const float4*)(Agp + (size_t)64 * Cc);
            a1[1] = *(const float4*)(Agp + (size_t)64 * Cc + 4);
            bv[0] = *(const float4*)(Bgp);
            bv[1] = *(const float4*)(Bgp + 4);
        }

        const uint32_t asb = as_base + (uint32_t)cur * 16384;
        const uint32_t bsb = bs_base + (uint32_t)cur * 8192;
#pragma unroll
        for (int ks = 0; ks < 2; ks++) {
            const int k0 = ks * 16;
            uint32_t ah[2][4], al[2][4], bhv[2][4], blv[2][4];
#pragma unroll
            for (int mf = 0; mf < 2; mf++) {
                const uint32_t rbase = asb + (uint32_t)(wm + mf * 16 + l15) * 128;
                const int ch = ((k0 >> 3) + lsel) ^ l7;
                const int cl = ((k0 >> 3) + lsel + 4) ^ l7;
                LDSM_X4(ah[mf][0], ah[mf][1], ah[mf][2], ah[mf][3], rbase + ch * 16);
                LDSM_X4(al[mf][0], al[mf][1], al[mf][2], al[mf][3], rbase + cl * 16);
            }
#pragma unroll
            for (int np = 0; np < 2; np++) {
                const int c = (wn >> 3) + np * 2 + lsel;
                const int p = c ^ l7;
                const uint32_t rb = bsb + (uint32_t)(k0 + l15) * 128 + p * 16;
                LDSM_X4_T(bhv[np][0], bhv[np][1], bhv[np][2], bhv[np][3], rb);
                LDSM_X4_T(blv[np][0], blv[np][1], blv[np][2], blv[np][3], rb + 32 * 128);
            }
            EMIT_MMAS_3PASS(acc, ah, al, bhv, blv)
        }

        if (kt + 1 < GNT) {
            const int nxt = cur ^ 1;
            uint4 h, l;
            split8(a0[0], a0[1], h, l);
            As4[nxt][arow][akseg ^ am7] = h;
            As4[nxt][arow][(akseg + 4) ^ am7] = l;
            split8(a1[0], a1[1], h, l);
            As4[nxt][arow + 64][akseg ^ am7] = h;
            As4[nxt][arow + 64][(akseg + 4) ^ am7] = l;
            split8(bv[0], bv[1], h, l);
            Bs4[nxt][bkrow][bnseg ^ bk7] = h;
            Bs4[nxt][bkrow + 32][bnseg ^ bk7] = l;
            __syncthreads();
        }
    }

#pragma unroll
    for (int mf = 0; mf < 2; mf++) {
        const int o = otile + wm + mf * 16 + g;
        const float b0v = bias[o], b1v = bias[o + 8];
        float* base = g_cp + (size_t)b * CNsz + (size_t)o * Nn + noff + wn + tc * 2;
#pragma unroll
        for (int nf = 0; nf < 4; nf++) {
            *(float2*)(base + nf * 8) =
                make_float2(acc[mf][nf][0] + b0v, acc[mf][nf][1] + b0v);
            *(float2*)(base + nf * 8 + 8 * Nn) =
                make_float2(acc[mf][nf][2] + b1v, acc[mf][nf][3] + b1v);
        }
    }
}

// ============================================================================
// Kernel 2: Mpart[b,h][d,d'] = sum_n cp[b,d*H+h,n] * cross[b,d'*H+h,n]
// ============================================================================
__global__ __launch_bounds__(256) void k_mpart(const float* __restrict__ cross)
{
    __shared__ float As[16][64];
    __shared__ float Bs[16][64];
    const int h = blockIdx.x;
    const int b = blockIdx.y;
    const int tid = threadIdx.x;
    const int r = tid >> 4, c = tid & 15;
    const int lr = tid >> 2, lk = (tid & 3) * 4;

    const float* Ab = g_cp + (size_t)b * CNsz + h * Nn;
    const float* Bp = cross + (size_t)b * CNsz + h * Nn;

    unsigned long long acc[4][2];
#pragma unroll
    for (int i = 0; i < 4; i++) { acc[i][0] = 0ull; acc[i][1] = 0ull; }

    for (int k0 = 0; k0 < Nn; k0 += 16) {
        float4 av = *(const float4*)(Ab + (size_t)lr * HN + k0 + lk);
        float4 bv = *(const float4*)(Bp + (size_t)lr * HN + k0 + lk);
        __syncthreads();
        As[lk + 0][lr] = av.x; As[lk + 1][lr] = av.y;
        As[lk + 2][lr] = av.z; As[lk + 3][lr] = av.w;
        Bs[lk + 0][lr] = bv.x; Bs[lk + 1][lr] = bv.y;
        Bs[lk + 2][lr] = bv.z; Bs[lk + 3][lr] = bv.w;
        __syncthreads();
#pragma unroll
        for (int k = 0; k < 16; k++) {
            float4 ar = *(const float4*)&As[k][r * 4];
            ulonglong2 bp = *(const ulonglong2*)&Bs[k][c * 4];
            unsigned long long sv;
            sv = splat2(ar.x);
            FMA_F32X2(acc[0][0], sv, bp.x, acc[0][0]);
            FMA_F32X2(acc[0][1], sv, bp.y, acc[0][1]);
            sv = splat2(ar.y);
            FMA_F32X2(acc[1][0], sv, bp.x, acc[1][0]);
            FMA_F32X2(acc[1][1], sv, bp.y, acc[1][1]);
            sv = splat2(ar.z);
            FMA_F32X2(acc[2][0], sv, bp.x, acc[2][0]);
            FMA_F32X2(acc[2][1], sv, bp.y, acc[2][1]);
            sv = splat2(ar.w);
            FMA_F32X2(acc[3][0], sv, bp.x, acc[3][0]);
            FMA_F32X2(acc[3][1], sv, bp.y, acc[3][1]);
        }
    }

    float* mp = g_Mpart + ((size_t)b * Hh + h) * 4096;
#pragma unroll
    for (int i = 0; i < 4; i++) {
        float2 lo = unpack2(acc[i][0]);
        float2 hi = unpack2(acc[i][1]);
        *(float4*)(mp + (size_t)(r * 4 + i) * 64 + c * 4) =
            make_float4(lo.x, lo.y, hi.x, hi.y);
    }
}

// ============================================================================
// Kernel 2b: Mt planes = split(SCALE * sum_h Mpart[b,h])^T, [b][d'][d] bf16.
// 256 blocks x 128 threads (full-chip single wave), explicit MLP=12 loads.
// ============================================================================
__global__ __launch_bounds__(128) void k_mred_t()
{
    const int idx = blockIdx.x * 128 + threadIdx.x;   // 32768
    const int b = idx >> 12;
    const int e = idx & 4095;        // e = d*64 + d'
    const int d = e >> 6, dp = e & 63;

    const float* mp = g_Mpart + ((size_t)b * Hh) * 4096 + e;
    float v[Hh];
#pragma unroll
    for (int h = 0; h < Hh; h++) v[h] = mp[(size_t)h * 4096];
    float s = 0.f;
#pragma unroll
    for (int h = 0; h < Hh; h++) s += v[h];
    s *= SCALE;
    __nv_bfloat16 hv = __float2bfloat16(s);
    __nv_bfloat16 lv = __float2bfloat16(s - __bfloat162float(hv));
    g_Mth[(size_t)b * 4096 + dp * 64 + d] = hv;
    g_Mtl[(size_t)b * 4096 + dp * 64 + d] = lv;
}

// ============================================================================
// Kernel 3: k_out_mma — U[m, d'] = sum_d X[d,m] * M[d,d'] on tensor cores.
// ============================================================================
__global__ __launch_bounds__(256) void k_out_mma(const float* __restrict__ x_ori)
{
    __shared__ uint4 As4[128][16];
    __shared__ uint4 BsH[64][8];
    __shared__ uint4 BsL[64][8];
    const int tid = threadIdx.x;
    const int wid = tid >> 5, lane = tid & 31;
    const int b = blockIdx.x / Hh;
    const int h = blockIdx.x % Hh;
    const int mhalf = blockIdx.y;

    const int wm = (wid >> 1) * 32;
    const int wn = (wid & 1) * 32;
    const int l7 = lane & 7, l15 = lane & 15, lsel = lane >> 4;
    const int ksel = (lane >> 3) & 1;
    const int rowNl = (lane & 7) + (lsel << 3);
    const int g = lane >> 2, tc = lane & 3;

    {
        const int d = tid >> 2;
        const int mseg = (tid & 3) * 32;
        const int d7 = d & 7;
        const float* xr = x_ori + (size_t)b * CNsz + (size_t)(d * Hh + h) * Nn
                          + mhalf * 128 + mseg;
        float4 v[8];
#pragma unroll
        for (int j = 0; j < 8; j++) v[j] = ((const float4*)xr)[j];
#pragma unroll
        for (int j = 0; j < 4; j++) {
            uint4 hi, lo;
            split8(v[2 * j], v[2 * j + 1], hi, lo);
            const int c = (mseg >> 3) + j;
            const int p = (c & 8) | ((c ^ d7) & 7);
            As4[d][p] = hi;
            As4[d + 64][p] = lo;
        }
    }
    {
#pragma unroll
        for (int r = 0; r < 2; r++) {
            const int i = tid + r * 256;
            const int dp = i >> 3, c = i & 7;
            const int p = c ^ (dp & 7);
            BsH[dp][p] = ((const uint4*)(g_Mth + (size_t)b * 4096))[i];
            BsL[dp][p] = ((const uint4*)(g_Mtl + (size_t)b * 4096))[i];
        }
    }
    __syncthreads();

    const uint32_t asb = smem_u32(&As4[0][0]);
    const uint32_t bhb = smem_u32(&BsH[0][0]);
    const uint32_t blb = smem_u32(&BsL[0][0]);

    float acc[2][4][4];
#pragma unroll
    for (int i = 0; i < 2; i++)
#pragma unroll
        for (int j = 0; j < 4; j++)
#pragma unroll
            for (int e = 0; e < 4; e++) acc[i][j][e] = 0.f;

#pragma unroll
    for (int ks = 0; ks < 4; ks++) {
        uint32_t ah[2][4], al[2][4], bhv[2][4], blv[2][4];
#pragma unroll
        for (int mf = 0; mf < 2; mf++) {
            const int c = ((wm + mf * 16) >> 3) + lsel;
            const int p = (c & 8) | ((c ^ l7) & 7);
            const uint32_t rowk = (uint32_t)(ks * 16 + l15);
            uint32_t t0, t1, t2, t3;
            LDSM_X4_T(t0, t1, t2, t3, asb + rowk * 256 + p * 16);
            ah[mf][0] = t0; ah[mf][1] = t2; ah[mf][2] = t1; ah[mf][3] = t3;
            LDSM_X4_T(t0, t1, t2, t3, asb + (rowk + 64) * 256 + p * 16);
            al[mf][0] = t0; al[mf][1] = t2; al[mf][2] = t1; al[mf][3] = t3;
        }
#pragma unroll
        for (int np = 0; np < 2; np++) {
            const int rowN = wn + np * 16 + rowNl;
            const int ch = (ks * 2 + ksel) ^ l7;
            LDSM_X4(bhv[np][0], bhv[np][1], bhv[np][2], bhv[np][3],
                    bhb + (uint32_t)rowN * 128 + ch * 16);
            LDSM_X4(blv[np][0], blv[np][1], blv[np][2], blv[np][3],
                    blb + (uint32_t)rowN * 128 + ch * 16);
        }
        EMIT_MMAS_3PASS(acc, ah, al, bhv, blv)
    }

    const int mbase = h * 256 + mhalf * 128;
#pragma unroll
    for (int mf = 0; mf < 2; mf++) {
#pragma unroll
        for (int rh = 0; rh < 2; rh++) {
            const int m = mbase + wm + mf * 16 + g + rh * 8;
            const int nf = m / Hh;
            const int hf = m - nf * Hh;
            const size_t rowoff = ((size_t)b * Nn + nf) * Cc + hf * Dd + wn + tc * 2;
#pragma unroll
            for (int j = 0; j < 4; j++) {
                const float e0 = acc[mf][j][2 * rh];
                const float e1 = acc[mf][j][2 * rh + 1];
                __nv_bfloat16 h0 = __float2bfloat16(e0);
                __nv_bfloat16 h1 = __float2bfloat16(e1);
                __nv_bfloat16 l0 = __float2bfloat16(e0 - __bfloat162float(h0));
                __nv_bfloat16 l1 = __float2bfloat16(e1 - __bfloat162float(h1));
                __nv_bfloat162 hh(h0, h1), ll(l0, l1);
                *(uint32_t*)(g_Uhi + rowoff + j * 8) = *reinterpret_cast<uint32_t*>(&hh);
                *(uint32_t*)(g_Ulo + rowoff + j * 8) = *reinterpret_cast<uint32_t*>(&ll);
            }
        }
    }
}

// ============================================================================
// Kernel 4: out = x_ori + b_dep + U @ W_dep^T, bf16 3-split tensor core.
// ============================================================================
__global__ __launch_bounds__(256, 2) void k_deproj_mma(
    const float* __restrict__ Wdep, const float* __restrict__ bdep,
    const float* __restrict__ x_ori, float* __restrict__ out)
{
    __shared__ uint4 As4[2][128][8];
    __shared__ uint4 Bs4[2][64][8];
    const int tid = threadIdx.x;
    const int wid = tid >> 5, lane = tid & 31;
    const int b = blockIdx.x >> 2;
    const int noff = (blockIdx.x & 3) * 64;
    const int otile = blockIdx.y * 128;

    const int wm = (wid >> 1) * 32;
    const int wn = (wid & 1) * 32;
    const int l7 = lane & 7, l15 = lane & 15, lsel = lane >> 4;
    const int ksel = (lane >> 3) & 1;
    const int rowNl = (lane & 7) + (lsel << 3);
    const int g = lane >> 2, tc = lane & 3;

    const int arow = tid >> 2, akseg = tid & 3;
    const int am7 = arow & 7;
    const int bnrow = tid >> 3, bc = tid & 7;
    const int bn7 = bnrow & 7;

    const float* Agp = Wdep + (size_t)(otile + arow) * Cc + akseg * 8;
    const __nv_bfloat16* Usrc = (bc < 4) ? g_Uhi : g_Ulo;
    const __nv_bfloat16* Ugp =
        Usrc + ((size_t)b * Nn + noff + bnrow) * Cc + (bc & 3) * 8;

    const uint32_t as_base = smem_u32(&As4[0][0][0]);
    const uint32_t bs_base = smem_u32(&Bs4[0][0][0]);

    float acc[2][4][4];
#pragma unroll
    for (int i = 0; i < 2; i++)
#pragma unroll
        for (int j = 0; j < 4; j++)
#pragma unroll
            for (int e = 0; e < 4; e++) acc[i][j][e] = 0.f;

    float4 a0[2], a1[2];
    uint4 u0, u1;
    a0[0] = *(const float4*)(Agp);
    a0[1] = *(const float4*)(Agp + 4);
    a1[0] = *(const float4*)(Agp + (size_t)64 * Cc);
    a1[1] = *(const float4*)(Agp + (size_t)64 * Cc + 4);
    u0 = *(const uint4*)(Ugp);
    u1 = *(const uint4*)(Ugp + (size_t)32 * Cc);

    {
        uint4 h, l;
        split8(a0[0], a0[1], h, l);
        As4[0][arow][akseg ^ am7] = h;
        As4[0][arow][(akseg + 4) ^ am7] = l;
        split8(a1[0], a1[1], h, l);
        As4[0][arow + 64][akseg ^ am7] = h;
        As4[0][arow + 64][(akseg + 4) ^ am7] = l;
        Bs4[0][bnrow][bc ^ bn7] = u0;
        Bs4[0][bnrow + 32][bc ^ bn7] = u1;
    }
    __syncthreads();

    for (int kt = 0; kt < GNT; kt++) {
        const int cur = kt & 1;
        if (kt + 1 < GNT) {
            Agp += 32;
            Ugp += 32;
            a0[0] = *(const float4*)(Agp);
            a0[1] = *(const float4*)(Agp + 4);
            a1[0] = *(const float4*)(Agp + (size_t)64 * Cc);
            a1[1] = *(const float4*)(Agp + (size_t)64 * Cc + 4);
            u0 = *(const uint4*)(Ugp);
            u1 = *(const uint4*)(Ugp + (size_t)32 * Cc);
        }

        const uint32_t asb = as_base + (uint32_t)cur * 16384;
        const uint32_t bsb = bs_base + (uint32_t)cur * 8192;
#pragma unroll
        for (int ks = 0; ks < 2; ks++) {
            const int k0 = ks * 16;
            uint32_t ah[2][4], al[2][4], bhv[2][4], blv[2][4];
#pragma unroll
            for (int mf = 0; mf < 2; mf++) {
                const uint32_t rbase = asb + (uint32_t)(wm + mf * 16 + l15) * 128;
                const int ch = ((k0 >> 3) + lsel) ^ l7;
                const int cl = ((k0 >> 3) + lsel + 4) ^ l7;
                LDSM_X4(ah[mf][0], ah[mf][1], ah[mf][2], ah[mf][3], rbase + ch * 16);
                LDSM_X4(al[mf][0], al[mf][1], al[mf][2], al[mf][3], rbase + cl * 16);
            }
#pragma unroll
            for (int np = 0; np < 2; np++) {
                const int rowN = wn + np * 16 + rowNl;
                const int ch = ((k0 >> 3) + ksel) ^ l7;
                const int cl = ((k0 >> 3) + ksel + 4) ^ l7;
                const uint32_t rb = bsb + (uint32_t)rowN * 128;
                LDSM_X4(bhv[np][0], bhv[np][1], bhv[np][2], bhv[np][3], rb + ch * 16);
                LDSM_X4(blv[np][0], blv[np][1], blv[np][2], blv[np][3], rb + cl * 16);
            }
            EMIT_MMAS_3PASS(acc, ah, al, bhv, blv)
        }

        if (kt + 1 < GNT) {
            const int nxt = cur ^ 1;
            uint4 h, l;
            split8(a0[0], a0[1], h, l);
            As4[nxt][arow][akseg ^ am7] = h;
            As4[nxt][arow][(akseg + 4) ^ am7] = l;
            split8(a1[0], a1[1], h, l);
            As4[nxt][arow + 64][akseg ^ am7] = h;
            As4[nxt][arow + 64][(akseg + 4) ^ am7] = l;
            Bs4[nxt][bnrow][bc ^ bn7] = u0;
            Bs4[nxt][bnrow + 32][bc ^ bn7] = u1;
            __syncthreads();
        }
    }

#pragma unroll
    for (int mf = 0; mf < 2; mf++) {
        const int o = otile + wm + mf * 16 + g;
        const float b0v = bdep[o], b1v = bdep[o + 8];
        const size_t base = (size_t)b * CNsz + (size_t)o * Nn + noff + wn + tc * 2;
#pragma unroll
        for (int nf = 0; nf < 4; nf++) {
            const size_t i0 = base + nf * 8;
            float2 x0 = *(const float2*)(x_ori + i0);
            float2 x1 = *(const float2*)(x_ori + i0 + 8 * Nn);
            *(float2*)(out + i0) =
                make_float2(acc[mf][nf][0] + b0v + x0.x, acc[mf][nf][1] + b0v + x0.y);
            *(float2*)(out + i0 + 8 * Nn) =
                make_float2(acc[mf][nf][2] + b1v + x1.x, acc[mf][nf][3] + b1v + x1.y);
        }
    }
}

// ============================================================================
// Launch
// ============================================================================
extern "C" void kernel_launch(void* const* d_in, const int* in_sizes, int n_in,
                              void* d_out, int out_size)
{
    (void)in_sizes; (void)n_in; (void)out_size;
    const float* x_ori  = (const float*)d_in[0];
    const float* cross  = (const float*)d_in[1];
    const float* W_proj = (const float*)d_in[2];
    const float* b_proj = (const float*)d_in[3];
    const float* W_dep  = (const float*)d_in[4];
    const float* b_dep  = (const float*)d_in[5];
    float* out = (float*)d_out;

    k_proj_mma<<<dim3(32, 6), 256>>>(W_proj, cross, b_proj);
    k_mpart<<<dim3(Hh, Bb), 256>>>(cross);
    k_mred_t<<<256, 128>>>();
    k_out_mma<<<dim3(Bb * Hh, 2), 256>>>(x_ori);
    k_deproj_mma<<<dim3(32, 6), 256>>>(W_dep, b_dep, x_ori, out);
}